// round 1
// baseline (speedup 1.0000x reference)
#include <cuda_runtime.h>
#include <math.h>
#include <stdint.h>

// Problem constants
#define BB 4
#define SS 4096
#define DD 1024
#define KW 4
#define MM (BB * SS)      // 16384 rows
#define N1 (2 * DD)       // 2048
#define EPSV 1e-6f

// Scratch (allocation-free rule: __device__ globals)
__device__ float g_h[(size_t)MM * DD];    // normalized x, later reused for gated y
__device__ float g_xz[(size_t)MM * N1];   // GEMM1 output [xb | z]
__device__ float g_hs[(size_t)MM * DD];   // recurrence output

// ---------------------------------------------------------------------------
// block-wide sum reduction (blockDim.x == 256)
// ---------------------------------------------------------------------------
__device__ __forceinline__ float block_reduce_sum(float v) {
    __shared__ float red[8];
    int lane = threadIdx.x & 31;
    int wid  = threadIdx.x >> 5;
    #pragma unroll
    for (int o = 16; o > 0; o >>= 1) v += __shfl_xor_sync(0xffffffffu, v, o);
    if (lane == 0) red[wid] = v;
    __syncthreads();
    if (wid == 0) {
        v = (lane < 8) ? red[lane] : 0.f;
        #pragma unroll
        for (int o = 4; o > 0; o >>= 1) v += __shfl_xor_sync(0xffffffffu, v, o);
        if (lane == 0) red[0] = v;
    }
    __syncthreads();
    return red[0];
}

__device__ __forceinline__ float silu_f(float v) {
    return v / (1.f + __expf(-v));
}

// ---------------------------------------------------------------------------
// Kernel 1: h = rmsnorm(x, norm_w).  One block per row, 256 threads, float4.
// ---------------------------------------------------------------------------
__global__ __launch_bounds__(256) void rmsnorm_kernel(
    const float* __restrict__ x, const float* __restrict__ w,
    float* __restrict__ out)
{
    size_t row = blockIdx.x;
    const float4* xr = (const float4*)(x + row * DD);
    float4 v = xr[threadIdx.x];
    float ss = v.x * v.x + v.y * v.y + v.z * v.z + v.w * v.w;
    ss = block_reduce_sum(ss);
    float scale = rsqrtf(ss * (1.f / DD) + EPSV);
    float4 wv = ((const float4*)w)[threadIdx.x];
    float4 o;
    o.x = v.x * scale * wv.x;
    o.y = v.y * scale * wv.y;
    o.z = v.z * scale * wv.z;
    o.w = v.w * scale * wv.w;
    ((float4*)(out + row * DD))[threadIdx.x] = o;
}

// ---------------------------------------------------------------------------
// Kernel 2/5: fp32 SGEMM, C[M,N] = A[M,K] @ B[K,N]  (row-major).
// 128x128 tile, BK=8, 256 threads, 8x8 per thread, A tile transposed in smem.
// Optional epilogue: C = rs * resid + acc  (resid != nullptr).
// M, N, K all multiples of tile sizes (no bounds checks).
// ---------------------------------------------------------------------------
__global__ __launch_bounds__(256) void sgemm128_kernel(
    int Nn, int Kk,
    const float* __restrict__ A, const float* __restrict__ Bm,
    float* __restrict__ C,
    const float* __restrict__ resid, const float* __restrict__ rs_ptr)
{
    const int BM = 128, BN = 128, BK = 8, TM = 8, TN = 8;
    __shared__ float As[BK * BM];
    __shared__ float Bs[BK * BN];

    int tid  = threadIdx.x;
    int cRow = blockIdx.y, cCol = blockIdx.x;

    const float* Ab = A + (size_t)cRow * BM * Kk;
    const float* Bb = Bm + (size_t)cCol * BN;
    size_t cOff = (size_t)cRow * BM * Nn + (size_t)cCol * BN;

    int innerRowA = tid >> 1;             // 0..127
    int innerColA = (tid & 1) * 4;        // 0 or 4
    int innerRowB = tid >> 5;             // 0..7
    int innerColB = (tid & 31) * 4;       // 0..124
    int threadRow = (tid >> 4) * TM;      // 0..120
    int threadCol = (tid & 15) * TN;      // 0..120

    float acc[TM][TN] = {};
    float regM[TM], regN[TN];

    for (int kt = 0; kt < Kk; kt += BK) {
        float4 av = *(const float4*)(Ab + (size_t)innerRowA * Kk + kt + innerColA);
        As[(innerColA + 0) * BM + innerRowA] = av.x;
        As[(innerColA + 1) * BM + innerRowA] = av.y;
        As[(innerColA + 2) * BM + innerRowA] = av.z;
        As[(innerColA + 3) * BM + innerRowA] = av.w;
        *(float4*)(&Bs[innerRowB * BN + innerColB]) =
            *(const float4*)(Bb + (size_t)(kt + innerRowB) * Nn + innerColB);
        __syncthreads();

        #pragma unroll
        for (int k = 0; k < BK; k++) {
            #pragma unroll
            for (int i = 0; i < TM; i += 4)
                *(float4*)&regM[i] = *(const float4*)&As[k * BM + threadRow + i];
            #pragma unroll
            for (int j = 0; j < TN; j += 4)
                *(float4*)&regN[j] = *(const float4*)&Bs[k * BN + threadCol + j];
            #pragma unroll
            for (int i = 0; i < TM; i++)
                #pragma unroll
                for (int j = 0; j < TN; j++)
                    acc[i][j] += regM[i] * regN[j];
        }
        __syncthreads();
    }

    float rs = 0.f;
    if (resid) rs = *rs_ptr;

    #pragma unroll
    for (int i = 0; i < TM; i++) {
        #pragma unroll
        for (int j = 0; j < TN; j += 4) {
            size_t off = cOff + (size_t)(threadRow + i) * Nn + threadCol + j;
            float4 v = make_float4(acc[i][j], acc[i][j + 1], acc[i][j + 2], acc[i][j + 3]);
            if (resid) {
                float4 r = *(const float4*)(resid + off);
                v.x = fmaf(rs, r.x, v.x);
                v.y = fmaf(rs, r.y, v.y);
                v.z = fmaf(rs, r.z, v.z);
                v.w = fmaf(rs, r.w, v.w);
            }
            *(float4*)(C + off) = v;
        }
    }
}

// ---------------------------------------------------------------------------
// Kernel 3: depthwise causal conv1d (K=4) + bias + SiLU + diagonal recurrence.
// One thread per (b, d): 4096 threads. xb = first half of xz rows.
// xc_t = silu(w0*x_{t-3} + w1*x_{t-2} + w2*x_{t-1} + w3*x_t + bias)
// h_t  = a * h_{t-1} + xc_t,  a = sigmoid(decay[d])
// ---------------------------------------------------------------------------
__global__ __launch_bounds__(256) void conv_scan_kernel(
    const float* __restrict__ xz, const float* __restrict__ conv_w,
    const float* __restrict__ conv_b, const float* __restrict__ decay,
    float* __restrict__ hs)
{
    int idx = blockIdx.x * blockDim.x + threadIdx.x;  // 0..4095
    int b = idx / DD;
    int d = idx % DD;

    float w0 = conv_w[d * KW + 0];
    float w1 = conv_w[d * KW + 1];
    float w2 = conv_w[d * KW + 2];
    float w3 = conv_w[d * KW + 3];
    float bias = conv_b[d];
    float a = 1.f / (1.f + __expf(-decay[d]));

    const float* xb = xz + (size_t)b * SS * N1 + d;   // stride N1 per timestep
    float* out = hs + (size_t)b * SS * DD + d;        // stride DD per timestep

    float x0 = 0.f, x1 = 0.f, x2 = 0.f;
    float h = 0.f;
    #pragma unroll 4
    for (int t = 0; t < SS; t++) {
        float x3 = xb[(size_t)t * N1];
        float c = fmaf(w0, x0, fmaf(w1, x1, fmaf(w2, x2, fmaf(w3, x3, bias))));
        c = silu_f(c);
        h = fmaf(a, h, c);
        out[(size_t)t * DD] = h;
        x0 = x1; x1 = x2; x2 = x3;
    }
}

// ---------------------------------------------------------------------------
// Kernel 4: y = rmsnorm(hs, gate_w) * silu(z).  One block per row.
// z = second half of xz rows. Writes y into g_h (reuse).
// ---------------------------------------------------------------------------
__global__ __launch_bounds__(256) void gate_kernel(
    const float* __restrict__ hs, const float* __restrict__ gate_w,
    const float* __restrict__ xz, float* __restrict__ y)
{
    size_t row = blockIdx.x;
    const float4* hr = (const float4*)(hs + row * DD);
    float4 v = hr[threadIdx.x];
    float ss = v.x * v.x + v.y * v.y + v.z * v.z + v.w * v.w;
    ss = block_reduce_sum(ss);
    float scale = rsqrtf(ss * (1.f / DD) + EPSV);

    float4 gw = ((const float4*)gate_w)[threadIdx.x];
    float4 zv = ((const float4*)(xz + row * N1 + DD))[threadIdx.x];
    float4 o;
    o.x = v.x * scale * gw.x * silu_f(zv.x);
    o.y = v.y * scale * gw.y * silu_f(zv.y);
    o.z = v.z * scale * gw.z * silu_f(zv.z);
    o.w = v.w * scale * gw.w * silu_f(zv.w);
    ((float4*)(y + row * DD))[threadIdx.x] = o;
}

// ---------------------------------------------------------------------------
// Host launcher
// ---------------------------------------------------------------------------
extern "C" void kernel_launch(void* const* d_in, const int* in_sizes, int n_in,
                              void* d_out, int out_size)
{
    const float* x         = (const float*)d_in[0];
    const float* norm_w    = (const float*)d_in[1];
    const float* in_w      = (const float*)d_in[2];
    const float* conv_w    = (const float*)d_in[3];
    const float* conv_b    = (const float*)d_in[4];
    const float* decay     = (const float*)d_in[5];
    const float* gate_w    = (const float*)d_in[6];
    const float* out_w     = (const float*)d_in[7];
    const float* res_scale = (const float*)d_in[8];
    float* out = (float*)d_out;

    float *p_h, *p_xz, *p_hs;
    cudaGetSymbolAddress((void**)&p_h,  g_h);
    cudaGetSymbolAddress((void**)&p_xz, g_xz);
    cudaGetSymbolAddress((void**)&p_hs, g_hs);

    // 1. h = rmsnorm(x)
    rmsnorm_kernel<<<MM, 256>>>(x, norm_w, p_h);

    // 2. xz = h @ in_w   [16384 x 2048]
    {
        dim3 grid(N1 / 128, MM / 128);
        sgemm128_kernel<<<grid, 256>>>(N1, DD, p_h, in_w, p_xz, nullptr, nullptr);
    }

    // 3. conv + silu + recurrence -> hs
    conv_scan_kernel<<<(BB * DD) / 256, 256>>>(p_xz, conv_w, conv_b, decay, p_hs);

    // 4. y = rmsnorm(hs, gate_w) * silu(z) -> g_h (reuse)
    gate_kernel<<<MM, 256>>>(p_hs, gate_w, p_xz, p_h);

    // 5. out = res_scale * x + y @ out_w   [16384 x 1024]
    {
        dim3 grid(DD / 128, MM / 128);
        sgemm128_kernel<<<grid, 256>>>(DD, DD, p_h, out_w, out, x, res_scale);
    }
}

// round 3
// speedup vs baseline: 4.6165x; 4.6165x over previous
#include <cuda_runtime.h>
#include <math.h>
#include <stdint.h>

// ---------------- problem constants ----------------
#define BB 4
#define SS 4096
#define DD 1024
#define KW 4
#define MM (BB * SS)      // 16384
#define N1 (2 * DD)       // 2048
#define EPSV 1e-6f
#define LCH 128           // scan chunk length
#define NCH (SS / LCH)    // 32

// ---------------- scratch (__device__ globals; no allocs) ----------------
__device__ float g_h  [(size_t)MM * DD];   // rmsnorm(x) -> later gated y (tf32-rounded)
__device__ float g_xz [(size_t)MM * N1];   // GEMM1 out [xb | z]
__device__ float g_hs [(size_t)MM * DD];   // scan output
__device__ float g_wt1[(size_t)N1 * DD];   // in_w^T  [2048,1024] tf32-rounded
__device__ float g_wt2[(size_t)DD * DD];   // out_w^T [1024,1024] tf32-rounded
__device__ float g_last[(size_t)BB * NCH * DD];
__device__ float g_sin [(size_t)BB * NCH * DD];

// ---------------- helpers ----------------
__device__ __forceinline__ float tf32r(float x) {
    uint32_t u; asm("cvt.rn.tf32.f32 %0, %1;" : "=r"(u) : "f"(x));
    return __uint_as_float(u);
}
__device__ __forceinline__ float silu_f(float v) { return v / (1.f + __expf(-v)); }

__device__ __forceinline__ uint32_t smem_u32(const void* p) {
    uint32_t a;
    asm("{ .reg .u64 t; cvta.to.shared.u64 t, %1; cvt.u32.u64 %0, t; }" : "=r"(a) : "l"(p));
    return a;
}
__device__ __forceinline__ void cp16(uint32_t s, const void* g) {
    asm volatile("cp.async.cg.shared.global [%0], [%1], 16;" :: "r"(s), "l"(g) : "memory");
}
__device__ __forceinline__ void cp_commit() {
    asm volatile("cp.async.commit_group;" ::: "memory");
}
__device__ __forceinline__ void cp_wait1() {
    asm volatile("cp.async.wait_group 1;" ::: "memory");
}
__device__ __forceinline__ void cp_wait0() {
    asm volatile("cp.async.wait_group 0;" ::: "memory");
}

__device__ __forceinline__ void mma_tf32(float* c, const uint32_t* a, uint32_t b0, uint32_t b1) {
    asm volatile(
        "mma.sync.aligned.m16n8k8.row.col.f32.tf32.tf32.f32 "
        "{%0,%1,%2,%3}, {%4,%5,%6,%7}, {%8,%9}, {%0,%1,%2,%3};"
        : "+f"(c[0]), "+f"(c[1]), "+f"(c[2]), "+f"(c[3])
        : "r"(a[0]), "r"(a[1]), "r"(a[2]), "r"(a[3]), "r"(b0), "r"(b1));
}

// ---------------- block reduction (256 threads) ----------------
__device__ __forceinline__ float block_reduce_sum(float v) {
    __shared__ float red[8];
    int lane = threadIdx.x & 31, wid = threadIdx.x >> 5;
    #pragma unroll
    for (int o = 16; o > 0; o >>= 1) v += __shfl_xor_sync(0xffffffffu, v, o);
    if (lane == 0) red[wid] = v;
    __syncthreads();
    if (wid == 0) {
        v = (lane < 8) ? red[lane] : 0.f;
        #pragma unroll
        for (int o = 4; o > 0; o >>= 1) v += __shfl_xor_sync(0xffffffffu, v, o);
        if (lane == 0) red[0] = v;
    }
    __syncthreads();
    return red[0];
}

// ---------------- weight transpose + tf32 round: out[N,K] = round(in[K,N]^T) ----------------
__global__ __launch_bounds__(256) void transpose_kernel(
    const float* __restrict__ in, float* __restrict__ out, int Nn)
{
    __shared__ float tile[32][33];
    int n0 = blockIdx.x * 32, k0 = blockIdx.y * 32;
    int tx = threadIdx.x & 31, ty = threadIdx.x >> 5;
    #pragma unroll
    for (int i = 0; i < 32; i += 8)
        tile[ty + i][tx] = in[(size_t)(k0 + ty + i) * Nn + n0 + tx];
    __syncthreads();
    #pragma unroll
    for (int i = 0; i < 32; i += 8)
        out[(size_t)(n0 + ty + i) * DD + k0 + tx] = tf32r(tile[tx][ty + i]);
}

// ---------------- rmsnorm (tf32-rounded output) ----------------
__global__ __launch_bounds__(256) void rmsnorm_kernel(
    const float* __restrict__ x, const float* __restrict__ w, float* __restrict__ out)
{
    size_t row = blockIdx.x;
    float4 v = ((const float4*)(x + row * DD))[threadIdx.x];
    float ss = v.x * v.x + v.y * v.y + v.z * v.z + v.w * v.w;
    ss = block_reduce_sum(ss);
    float s = rsqrtf(ss * (1.f / DD) + EPSV);
    float4 wv = ((const float4*)w)[threadIdx.x];
    float4 o;
    o.x = tf32r(v.x * s * wv.x); o.y = tf32r(v.y * s * wv.y);
    o.z = tf32r(v.z * s * wv.z); o.w = tf32r(v.w * s * wv.w);
    ((float4*)(out + row * DD))[threadIdx.x] = o;
}

// ---------------- tf32 mma.sync GEMM ----------------
// C[M,N] = A[M,1024] @ Bt[N,1024]^T ; optional C += rs*resid
// 128x128 tile, BK=32, 3-stage cp.async, 8 warps (4x2), warp tile 32x64.
#define BKK 32
#define ASTR 36                      // padded float stride
#define SSTRIDE (128 * ASTR)         // floats per (A or B) stage
#define GSTG 3
#define GEMM_SMEM (GSTG * 2 * SSTRIDE * 4)

__global__ __launch_bounds__(256, 1) void gemm_tc_kernel(
    int Nn, const float* __restrict__ A, const float* __restrict__ Bt,
    float* __restrict__ C,
    const float* __restrict__ resid, const float* __restrict__ rs_ptr)
{
    extern __shared__ float sm[];
    const int tid = threadIdx.x, lane = tid & 31, wid = tid >> 5;
    const int mtile = blockIdx.y * 128, ntile = blockIdx.x * 128;
    const int wm = (wid & 3) * 32, wn = (wid >> 2) * 64;

    // loader mapping: 32 rows per pass, 4 passes; 8 threads x 16B per row
    const int lr = tid >> 3;            // 0..31
    const int lc = (tid & 7) * 4;       // 0,4,...,28

    const float* Ag = A  + (size_t)(mtile + lr) * DD + lc;
    const float* Bg = Bt + (size_t)(ntile + lr) * DD + lc;

    uint32_t smb = smem_u32(sm);

    auto stage_load = [&](int s, int kc) {
        uint32_t as = smb + (uint32_t)(s * 2 * SSTRIDE) * 4;
        uint32_t bs = as + SSTRIDE * 4;
        #pragma unroll
        for (int i = 0; i < 4; i++) {
            uint32_t so = (uint32_t)((lr + i * 32) * ASTR + lc) * 4;
            cp16(as + so, Ag + (size_t)i * 32 * DD + kc * BKK);
            cp16(bs + so, Bg + (size_t)i * 32 * DD + kc * BKK);
        }
        cp_commit();
    };

    float acc[2][8][4];
    #pragma unroll
    for (int mi = 0; mi < 2; mi++)
        #pragma unroll
        for (int ni = 0; ni < 8; ni++)
            #pragma unroll
            for (int j = 0; j < 4; j++) acc[mi][ni][j] = 0.f;

    const int NKC = DD / BKK;           // 32
    stage_load(0, 0);
    stage_load(1, 1);

    const int fr = lane >> 2, fc = lane & 3;

    for (int kc = 0; kc < NKC; kc++) {
        cp_wait1();
        __syncthreads();
        if (kc + 2 < NKC) stage_load((kc + 2) % GSTG, kc + 2);

        const float* as = sm + (kc % GSTG) * 2 * SSTRIDE + (wm + fr) * ASTR + fc;
        const float* bs = sm + (kc % GSTG) * 2 * SSTRIDE + SSTRIDE + (wn + fr) * ASTR + fc;

        #pragma unroll
        for (int kk = 0; kk < 4; kk++) {
            const int k0 = kk * 8;
            uint32_t a[2][4];
            #pragma unroll
            for (int mi = 0; mi < 2; mi++) {
                const float* ap = as + mi * 16 * ASTR + k0;
                a[mi][0] = __float_as_uint(ap[0]);
                a[mi][1] = __float_as_uint(ap[8 * ASTR]);
                a[mi][2] = __float_as_uint(ap[4]);
                a[mi][3] = __float_as_uint(ap[8 * ASTR + 4]);
            }
            #pragma unroll
            for (int ni = 0; ni < 8; ni++) {
                const float* bp = bs + ni * 8 * ASTR + k0;
                uint32_t b0 = __float_as_uint(bp[0]);
                uint32_t b1 = __float_as_uint(bp[4]);
                mma_tf32(acc[0][ni], a[0], b0, b1);
                mma_tf32(acc[1][ni], a[1], b0, b1);
            }
        }
        __syncthreads();
    }
    cp_wait0();

    // epilogue
    float rs = 0.f;
    if (resid) rs = __ldg(rs_ptr);
    #pragma unroll
    for (int mi = 0; mi < 2; mi++) {
        #pragma unroll
        for (int half = 0; half < 2; half++) {
            int row = mtile + wm + mi * 16 + half * 8 + fr;
            #pragma unroll
            for (int ni = 0; ni < 8; ni++) {
                int col = ntile + wn + ni * 8 + fc * 2;
                size_t off = (size_t)row * Nn + col;
                float2 v = make_float2(acc[mi][ni][half * 2], acc[mi][ni][half * 2 + 1]);
                if (resid) {
                    float2 rv = *(const float2*)(resid + off);
                    v.x = fmaf(rs, rv.x, v.x);
                    v.y = fmaf(rs, rv.y, v.y);
                }
                *(float2*)(C + off) = v;
            }
        }
    }
}

// ---------------- scan phase 1: local conv+silu+scan per 128-chunk ----------------
__global__ __launch_bounds__(256) void conv_local_kernel(
    const float* __restrict__ xz, const float* __restrict__ conv_w,
    const float* __restrict__ conv_b, const float* __restrict__ decay,
    float* __restrict__ hs, float* __restrict__ last)
{
    int idx = blockIdx.x * blockDim.x + threadIdx.x;   // BB*NCH*DD
    int d = idx % DD;
    int ch = (idx / DD) % NCH;
    int b = idx / (DD * NCH);

    float w0 = conv_w[d * KW + 0], w1 = conv_w[d * KW + 1];
    float w2 = conv_w[d * KW + 2], w3 = conv_w[d * KW + 3];
    float bias = conv_b[d];
    float a = 1.f / (1.f + __expf(-decay[d]));

    int t0 = ch * LCH;
    const float* xb = xz + ((size_t)b * SS + t0) * N1 + d;
    float* out = hs + ((size_t)b * SS + t0) * DD + d;

    float x0 = 0.f, x1 = 0.f, x2 = 0.f;
    if (ch > 0) {
        x0 = xb[-3 * (ptrdiff_t)N1];
        x1 = xb[-2 * (ptrdiff_t)N1];
        x2 = xb[-1 * (ptrdiff_t)N1];
    }
    float h = 0.f;
    #pragma unroll 4
    for (int t = 0; t < LCH; t++) {
        float x3 = xb[(size_t)t * N1];
        float c = fmaf(w0, x0, fmaf(w1, x1, fmaf(w2, x2, fmaf(w3, x3, bias))));
        c = silu_f(c);
        h = fmaf(a, h, c);
        out[(size_t)t * DD] = h;
        x0 = x1; x1 = x2; x2 = x3;
    }
    last[((size_t)b * NCH + ch) * DD + d] = h;
}

// ---------------- scan phase 2: carry chain ----------------
__global__ __launch_bounds__(256) void carry_kernel(
    const float* __restrict__ decay, const float* __restrict__ last,
    float* __restrict__ sin_)
{
    int idx = blockIdx.x * blockDim.x + threadIdx.x;   // BB*DD
    int d = idx % DD, b = idx / DD;
    float a = 1.f / (1.f + __expf(-decay[d]));
    float aL = a;
    #pragma unroll
    for (int i = 0; i < 7; i++) aL *= aL;              // a^128
    float c = 0.f;
    for (int j = 0; j < NCH; j++) {
        size_t o = ((size_t)b * NCH + j) * DD + d;
        sin_[o] = c;
        c = fmaf(aL, c, last[o]);
    }
}

// ---------------- scan phase 3: apply carries ----------------
__global__ __launch_bounds__(256) void fix_kernel(
    const float* __restrict__ decay, const float* __restrict__ sin_,
    float* __restrict__ hs)
{
    int idx = blockIdx.x * blockDim.x + threadIdx.x;   // BB*NCH*DD
    int d = idx % DD;
    int ch = (idx / DD) % NCH;
    int b = idx / (DD * NCH);
    float s = sin_[((size_t)b * NCH + ch) * DD + d];
    if (s == 0.f) return;
    float a = 1.f / (1.f + __expf(-decay[d]));
    float f = a * s;
    float* p = hs + ((size_t)b * SS + ch * LCH) * DD + d;
    for (int t = 0; t < LCH; t++) {
        if (fabsf(f) < 1e-14f) break;
        p[(size_t)t * DD] += f;
        f *= a;
    }
}

// ---------------- gated rmsnorm (tf32-rounded output) ----------------
__global__ __launch_bounds__(256) void gate_kernel(
    const float* __restrict__ hs, const float* __restrict__ gate_w,
    const float* __restrict__ xz, float* __restrict__ y)
{
    size_t row = blockIdx.x;
    float4 v = ((const float4*)(hs + row * DD))[threadIdx.x];
    float ss = v.x * v.x + v.y * v.y + v.z * v.z + v.w * v.w;
    ss = block_reduce_sum(ss);
    float s = rsqrtf(ss * (1.f / DD) + EPSV);
    float4 gw = ((const float4*)gate_w)[threadIdx.x];
    float4 zv = ((const float4*)(xz + row * N1 + DD))[threadIdx.x];
    float4 o;
    o.x = tf32r(v.x * s * gw.x * silu_f(zv.x));
    o.y = tf32r(v.y * s * gw.y * silu_f(zv.y));
    o.z = tf32r(v.z * s * gw.z * silu_f(zv.z));
    o.w = tf32r(v.w * s * gw.w * silu_f(zv.w));
    ((float4*)(y + row * DD))[threadIdx.x] = o;
}

// ---------------- host ----------------
extern "C" void kernel_launch(void* const* d_in, const int* in_sizes, int n_in,
                              void* d_out, int out_size)
{
    const float* x         = (const float*)d_in[0];
    const float* norm_w    = (const float*)d_in[1];
    const float* in_w      = (const float*)d_in[2];
    const float* conv_w    = (const float*)d_in[3];
    const float* conv_b    = (const float*)d_in[4];
    const float* decay     = (const float*)d_in[5];
    const float* gate_w    = (const float*)d_in[6];
    const float* out_w     = (const float*)d_in[7];
    const float* res_scale = (const float*)d_in[8];
    float* out = (float*)d_out;

    float *p_h, *p_xz, *p_hs, *p_wt1, *p_wt2, *p_last, *p_sin;
    cudaGetSymbolAddress((void**)&p_h,    g_h);
    cudaGetSymbolAddress((void**)&p_xz,   g_xz);
    cudaGetSymbolAddress((void**)&p_hs,   g_hs);
    cudaGetSymbolAddress((void**)&p_wt1,  g_wt1);
    cudaGetSymbolAddress((void**)&p_wt2,  g_wt2);
    cudaGetSymbolAddress((void**)&p_last, g_last);
    cudaGetSymbolAddress((void**)&p_sin,  g_sin);

    static bool smem_set = false;
    if (!smem_set) {
        cudaFuncSetAttribute(gemm_tc_kernel,
                             cudaFuncAttributeMaxDynamicSharedMemorySize, GEMM_SMEM);
        smem_set = true;
    }

    // 0. transpose + tf32-round weights
    transpose_kernel<<<dim3(N1 / 32, DD / 32), 256>>>(in_w,  p_wt1, N1);
    transpose_kernel<<<dim3(DD / 32, DD / 32), 256>>>(out_w, p_wt2, DD);

    // 1. h = rmsnorm(x) (tf32-rounded)
    rmsnorm_kernel<<<MM, 256>>>(x, norm_w, p_h);

    // 2. xz = h @ in_w
    gemm_tc_kernel<<<dim3(N1 / 128, MM / 128), 256, GEMM_SMEM>>>(
        N1, p_h, p_wt1, p_xz, nullptr, nullptr);

    // 3. chunked conv + scan
    conv_local_kernel<<<(BB * NCH * DD) / 256, 256>>>(p_xz, conv_w, conv_b, decay, p_hs, p_last);
    carry_kernel<<<(BB * DD) / 256, 256>>>(decay, p_last, p_sin);
    fix_kernel<<<(BB * NCH * DD) / 256, 256>>>(decay, p_sin, p_hs);

    // 4. y = rmsnorm(hs)*silu(z) (tf32-rounded) -> g_h
    gate_kernel<<<MM, 256>>>(p_hs, gate_w, p_xz, p_h);

    // 5. out = res_scale*x + y @ out_w
    gemm_tc_kernel<<<dim3(DD / 128, MM / 128), 256, GEMM_SMEM>>>(
        DD, p_h, p_wt2, out, x, res_scale);
}